// round 1
// baseline (speedup 1.0000x reference)
#include <cuda_runtime.h>
#include <math.h>
#include <stdint.h>

// Problem dims
#define BB 2
#define SS 2048
#define EE 1024
#define HH 16
#define DD 64
#define MM (BB * SS)      // 4096 rows
#define NQKV (3 * EE)     // 3072

// ---------------- scratch (static device globals; no allocation) ----------------
__device__ float g_q[BB * HH * SS * DD];   // [B,H,S,D]
__device__ float g_k[BB * HH * SS * DD];
__device__ float g_v[BB * HH * SS * DD];
__device__ float g_ctx[MM * EE];           // [B,S,E] attention context pre-proj

// =================================================================================
// Kernel 1: QKV = X @ W + b, scattered into g_q/g_k/g_v as [B,H,S,D]
// X: [4096,1024] row-major, W: [1024,3072] row-major
// BM=BN=128, BK=16, 256 threads, 8x8 micro-tile (split 4+4 pattern)
// =================================================================================
__global__ __launch_bounds__(256) void qkv_gemm_kernel(
    const float* __restrict__ X, const float* __restrict__ W,
    const float* __restrict__ bias)
{
    __shared__ float As[16][132];   // k-major (transposed A tile)
    __shared__ float Bs[16][132];

    const int bn = blockIdx.x, bm = blockIdx.y;
    const int tid = threadIdx.x;
    const int tx = tid & 15, ty = tid >> 4;
    const int row0 = bm * 128, col0 = bn * 128;

    float acc[8][8];
#pragma unroll
    for (int i = 0; i < 8; i++)
#pragma unroll
        for (int j = 0; j < 8; j++) acc[i][j] = 0.f;

    for (int k0 = 0; k0 < EE; k0 += 16) {
        // A tile: 128 x 16 (transpose into As[k][m])
#pragma unroll
        for (int it = 0; it < 2; it++) {
            int f4 = tid + it * 256;            // 0..511
            int r = f4 >> 2;
            int c = (f4 & 3) << 2;
            float4 v = *(const float4*)(X + (size_t)(row0 + r) * EE + k0 + c);
            As[c + 0][r] = v.x; As[c + 1][r] = v.y;
            As[c + 2][r] = v.z; As[c + 3][r] = v.w;
        }
        // B tile: 16 x 128
#pragma unroll
        for (int it = 0; it < 2; it++) {
            int f4 = tid + it * 256;
            int kk = f4 >> 5;
            int c = (f4 & 31) << 2;
            *(float4*)&Bs[kk][c] = *(const float4*)(W + (size_t)(k0 + kk) * NQKV + col0 + c);
        }
        __syncthreads();

#pragma unroll 8
        for (int k = 0; k < 16; k++) {
            float a[8], b[8];
            *(float4*)(a)     = *(float4*)&As[k][ty * 4];
            *(float4*)(a + 4) = *(float4*)&As[k][64 + ty * 4];
            *(float4*)(b)     = *(float4*)&Bs[k][tx * 4];
            *(float4*)(b + 4) = *(float4*)&Bs[k][64 + tx * 4];
#pragma unroll
            for (int i = 0; i < 8; i++)
#pragma unroll
                for (int j = 0; j < 8; j++) acc[i][j] += a[i] * b[j];
        }
        __syncthreads();
    }

    // epilogue: add bias, scatter to [B,H,S,D]
#pragma unroll
    for (int i = 0; i < 8; i++) {
        int r = row0 + ((i & 4) ? 64 : 0) + (ty << 2) + (i & 3);
        int b_ = r >> 11;          // / 2048
        int s  = r & 2047;
#pragma unroll
        for (int j = 0; j < 8; j++) {
            int n = col0 + ((j & 4) ? 64 : 0) + (tx << 2) + (j & 3);
            float v = acc[i][j] + bias[n];
            int which = n >> 10;   // 0=q 1=k 2=v
            int e = n & 1023;
            int h = e >> 6, d = e & 63;
            float* dst = (which == 0) ? g_q : (which == 1) ? g_k : g_v;
            dst[(size_t)(((b_ * HH) + h) * SS + s) * DD + d] = v;
        }
    }
}

// =================================================================================
// Kernel 2: fused causal attention per (q-block, head, batch).
// Two passes over key blocks: pass 1 = row stats (max, sumexp), pass 2 = exact
// softmax probs -> attn_weights gmem + SMEM, then O += P @ V. Zero-fills the
// upper triangle. Writes context to g_ctx as [B,S,E].
// =================================================================================
#define QS_OFF 0
#define KS_OFF (64 * 132)                    // 8448
#define VS_OFF (KS_OFF + 64 * 132)           // 16896
#define PS_OFF (VS_OFF + 128 * 68)           // 25600
#define SMEM_FLOATS (PS_OFF + 128 * 132)     // 42496
#define SMEM_BYTES (SMEM_FLOATS * 4)         // 169984

extern __shared__ float smbuf[];

__global__ __launch_bounds__(256) void attn_kernel(float* __restrict__ attn_w)
{
    float* Qs = smbuf + QS_OFF;   // [64][132] d-major
    float* Ks = smbuf + KS_OFF;   // [64][132] d-major
    float* Vs = smbuf + VS_OFF;   // [128][68] row-major
    float* Ps = smbuf + PS_OFF;   // [128][132]

    const int qb = blockIdx.x, h = blockIdx.y, b = blockIdx.z;
    const int tid = threadIdx.x;
    const int tx = tid & 15, ty = tid >> 4;
    const float scale = 0.125f;   // 1/sqrt(64)

    const float* Qg = g_q + (size_t)((b * HH + h) * SS) * DD;
    const float* Kg = g_k + (size_t)((b * HH + h) * SS) * DD;
    const float* Vg = g_v + (size_t)((b * HH + h) * SS) * DD;

    // load Q block transposed: Qs[d][r]
#pragma unroll
    for (int it = 0; it < 8; it++) {
        int f4 = tid + it * 256;            // 0..2047
        int r = f4 >> 4;
        int c = (f4 & 15) << 2;
        float4 v = *(const float4*)(Qg + (size_t)(qb * 128 + r) * DD + c);
        Qs[(c + 0) * 132 + r] = v.x; Qs[(c + 1) * 132 + r] = v.y;
        Qs[(c + 2) * 132 + r] = v.z; Qs[(c + 3) * 132 + r] = v.w;
    }
    __syncthreads();

    float m_run[8], l_run[8];
#pragma unroll
    for (int i = 0; i < 8; i++) { m_run[i] = -INFINITY; l_run[i] = 0.f; }

    // ---------------- pass 1: row max + sumexp ----------------
    for (int kb = 0; kb <= qb; kb++) {
#pragma unroll
        for (int it = 0; it < 8; it++) {
            int f4 = tid + it * 256;
            int r = f4 >> 4;
            int c = (f4 & 15) << 2;
            float4 v = *(const float4*)(Kg + (size_t)(kb * 128 + r) * DD + c);
            Ks[(c + 0) * 132 + r] = v.x; Ks[(c + 1) * 132 + r] = v.y;
            Ks[(c + 2) * 132 + r] = v.z; Ks[(c + 3) * 132 + r] = v.w;
        }
        __syncthreads();

        float acc[8][8];
#pragma unroll
        for (int i = 0; i < 8; i++)
#pragma unroll
            for (int j = 0; j < 8; j++) acc[i][j] = 0.f;

#pragma unroll 8
        for (int d = 0; d < 64; d++) {
            float a[8], bb[8];
            *(float4*)(a)      = *(float4*)&Qs[d * 132 + ty * 4];
            *(float4*)(a + 4)  = *(float4*)&Qs[d * 132 + 64 + ty * 4];
            *(float4*)(bb)     = *(float4*)&Ks[d * 132 + tx * 4];
            *(float4*)(bb + 4) = *(float4*)&Ks[d * 132 + 64 + tx * 4];
#pragma unroll
            for (int i = 0; i < 8; i++)
#pragma unroll
                for (int j = 0; j < 8; j++) acc[i][j] += a[i] * bb[j];
        }

        const bool diag = (kb == qb);
#pragma unroll
        for (int i = 0; i < 8; i++) {
            int r = ((i & 4) ? 64 : 0) + (ty << 2) + (i & 3);
            float s8[8];
            float mloc = -INFINITY;
#pragma unroll
            for (int j = 0; j < 8; j++) {
                int c = ((j & 4) ? 64 : 0) + (tx << 2) + (j & 3);
                float sv = acc[i][j] * scale;
                if (diag && c > r) sv = -INFINITY;
                s8[j] = sv;
                mloc = fmaxf(mloc, sv);
            }
#pragma unroll
            for (int o = 1; o < 16; o <<= 1)
                mloc = fmaxf(mloc, __shfl_xor_sync(0xffffffffu, mloc, o));
            float m_new = fmaxf(m_run[i], mloc);
            float lsum = 0.f;
#pragma unroll
            for (int j = 0; j < 8; j++) lsum += __expf(s8[j] - m_new);
#pragma unroll
            for (int o = 1; o < 16; o <<= 1)
                lsum += __shfl_xor_sync(0xffffffffu, lsum, o);
            l_run[i] = l_run[i] * __expf(m_run[i] - m_new) + lsum;
            m_run[i] = m_new;
        }
        __syncthreads();
    }

    float inv_l[8];
#pragma unroll
    for (int i = 0; i < 8; i++) inv_l[i] = 1.f / l_run[i];

    float accO[8][4];
#pragma unroll
    for (int i = 0; i < 8; i++)
#pragma unroll
        for (int j = 0; j < 4; j++) accO[i][j] = 0.f;

    const size_t wbase_bh = (size_t)(b * HH + h) * SS * SS;

    // ---------------- pass 2: probs -> gmem + smem, O += P @ V ----------------
    for (int kb = 0; kb <= qb; kb++) {
#pragma unroll
        for (int it = 0; it < 8; it++) {
            int f4 = tid + it * 256;
            int r = f4 >> 4;
            int c = (f4 & 15) << 2;
            float4 v = *(const float4*)(Kg + (size_t)(kb * 128 + r) * DD + c);
            Ks[(c + 0) * 132 + r] = v.x; Ks[(c + 1) * 132 + r] = v.y;
            Ks[(c + 2) * 132 + r] = v.z; Ks[(c + 3) * 132 + r] = v.w;
            *(float4*)&Vs[r * 68 + c] = *(const float4*)(Vg + (size_t)(kb * 128 + r) * DD + c);
        }
        __syncthreads();

        float acc[8][8];
#pragma unroll
        for (int i = 0; i < 8; i++)
#pragma unroll
            for (int j = 0; j < 8; j++) acc[i][j] = 0.f;

#pragma unroll 8
        for (int d = 0; d < 64; d++) {
            float a[8], bb[8];
            *(float4*)(a)      = *(float4*)&Qs[d * 132 + ty * 4];
            *(float4*)(a + 4)  = *(float4*)&Qs[d * 132 + 64 + ty * 4];
            *(float4*)(bb)     = *(float4*)&Ks[d * 132 + tx * 4];
            *(float4*)(bb + 4) = *(float4*)&Ks[d * 132 + 64 + tx * 4];
#pragma unroll
            for (int i = 0; i < 8; i++)
#pragma unroll
                for (int j = 0; j < 8; j++) acc[i][j] += a[i] * bb[j];
        }

        const bool diag = (kb == qb);
#pragma unroll
        for (int i = 0; i < 8; i++) {
            int r = ((i & 4) ? 64 : 0) + (ty << 2) + (i & 3);
            float p[8];
#pragma unroll
            for (int j = 0; j < 8; j++) {
                int c = ((j & 4) ? 64 : 0) + (tx << 2) + (j & 3);
                float sv = acc[i][j] * scale;
                float pv = (diag && c > r) ? 0.f : __expf(sv - m_run[i]) * inv_l[i];
                p[j] = pv;
                Ps[r * 132 + c] = pv;
            }
            size_t gb = wbase_bh + (size_t)(qb * 128 + r) * SS + kb * 128;
            *(float4*)(attn_w + gb + tx * 4)      = make_float4(p[0], p[1], p[2], p[3]);
            *(float4*)(attn_w + gb + 64 + tx * 4) = make_float4(p[4], p[5], p[6], p[7]);
        }
        __syncthreads();

        // O += Ps[128,128] @ Vs[128,64]; thread cols = tx*4..tx*4+3
#pragma unroll 8
        for (int k = 0; k < 128; k++) {
            float bv[4];
            *(float4*)bv = *(float4*)&Vs[k * 68 + tx * 4];
#pragma unroll
            for (int i = 0; i < 8; i++) {
                int r = ((i & 4) ? 64 : 0) + (ty << 2) + (i & 3);
                float pv = Ps[r * 132 + k];
#pragma unroll
                for (int j = 0; j < 4; j++) accO[i][j] += pv * bv[j];
            }
        }
        __syncthreads();
    }

    // zero-fill causal upper triangle (d_out is poisoned)
    const float4 z4 = make_float4(0.f, 0.f, 0.f, 0.f);
    for (int kb = qb + 1; kb < SS / 128; kb++) {
#pragma unroll
        for (int i = 0; i < 8; i++) {
            int r = ((i & 4) ? 64 : 0) + (ty << 2) + (i & 3);
            size_t gb = wbase_bh + (size_t)(qb * 128 + r) * SS + kb * 128;
            *(float4*)(attn_w + gb + tx * 4)      = z4;
            *(float4*)(attn_w + gb + 64 + tx * 4) = z4;
        }
    }

    // write O to g_ctx [B,S,E] at column h*64
#pragma unroll
    for (int i = 0; i < 8; i++) {
        int r = ((i & 4) ? 64 : 0) + (ty << 2) + (i & 3);
        int q = qb * 128 + r;
        size_t base = (size_t)(b * SS + q) * EE + h * 64 + tx * 4;
        *(float4*)&g_ctx[base] = make_float4(accO[i][0], accO[i][1], accO[i][2], accO[i][3]);
    }
}

// =================================================================================
// Kernel 3: out = ctx @ Wp + bp   (4096x1024 @ 1024x1024)
// =================================================================================
__global__ __launch_bounds__(256) void proj_gemm_kernel(
    const float* __restrict__ W, const float* __restrict__ bias,
    float* __restrict__ out)
{
    __shared__ float As[16][132];
    __shared__ float Bs[16][132];

    const int bn = blockIdx.x, bm = blockIdx.y;
    const int tid = threadIdx.x;
    const int tx = tid & 15, ty = tid >> 4;
    const int row0 = bm * 128, col0 = bn * 128;

    float acc[8][8];
#pragma unroll
    for (int i = 0; i < 8; i++)
#pragma unroll
        for (int j = 0; j < 8; j++) acc[i][j] = 0.f;

    for (int k0 = 0; k0 < EE; k0 += 16) {
#pragma unroll
        for (int it = 0; it < 2; it++) {
            int f4 = tid + it * 256;
            int r = f4 >> 2;
            int c = (f4 & 3) << 2;
            float4 v = *(const float4*)(g_ctx + (size_t)(row0 + r) * EE + k0 + c);
            As[c + 0][r] = v.x; As[c + 1][r] = v.y;
            As[c + 2][r] = v.z; As[c + 3][r] = v.w;
        }
#pragma unroll
        for (int it = 0; it < 2; it++) {
            int f4 = tid + it * 256;
            int kk = f4 >> 5;
            int c = (f4 & 31) << 2;
            *(float4*)&Bs[kk][c] = *(const float4*)(W + (size_t)(k0 + kk) * EE + col0 + c);
        }
        __syncthreads();

#pragma unroll 8
        for (int k = 0; k < 16; k++) {
            float a[8], b[8];
            *(float4*)(a)     = *(float4*)&As[k][ty * 4];
            *(float4*)(a + 4) = *(float4*)&As[k][64 + ty * 4];
            *(float4*)(b)     = *(float4*)&Bs[k][tx * 4];
            *(float4*)(b + 4) = *(float4*)&Bs[k][64 + tx * 4];
#pragma unroll
            for (int i = 0; i < 8; i++)
#pragma unroll
                for (int j = 0; j < 8; j++) acc[i][j] += a[i] * b[j];
        }
        __syncthreads();
    }

#pragma unroll
    for (int i = 0; i < 8; i++) {
        int r = row0 + ((i & 4) ? 64 : 0) + (ty << 2) + (i & 3);
#pragma unroll
        for (int j = 0; j < 8; j++) {
            int n = col0 + ((j & 4) ? 64 : 0) + (tx << 2) + (j & 3);
            out[(size_t)r * EE + n] = acc[i][j] + bias[n];
        }
    }
}

// =================================================================================
// launch
// =================================================================================
extern "C" void kernel_launch(void* const* d_in, const int* in_sizes, int n_in,
                              void* d_out, int out_size)
{
    const float* hs = (const float*)d_in[0];   // [2,2048,1024]
    const float* aw = (const float*)d_in[1];   // [1024,3072]
    const float* ab = (const float*)d_in[2];   // [3072]
    const float* pw = (const float*)d_in[3];   // [1024,1024]
    const float* pb = (const float*)d_in[4];   // [1024]

    float* out      = (float*)d_out;
    float* attn_out = out;                         // [2,2048,1024]
    float* attn_w   = out + (size_t)MM * EE;       // [2,16,2048,2048]

    cudaFuncSetAttribute(attn_kernel, cudaFuncAttributeMaxDynamicSharedMemorySize,
                         SMEM_BYTES);

    qkv_gemm_kernel<<<dim3(NQKV / 128, MM / 128), 256>>>(hs, aw, ab);
    attn_kernel<<<dim3(SS / 128, HH, BB), 256, SMEM_BYTES>>>(attn_w);
    proj_gemm_kernel<<<dim3(EE / 128, MM / 128), 256>>>(pw, pb, attn_out);
}

// round 2
// speedup vs baseline: 1.1077x; 1.1077x over previous
#include <cuda_runtime.h>
#include <math.h>
#include <stdint.h>

// Problem dims
#define BB 2
#define SS 2048
#define EE 1024
#define HH 16
#define DD 64
#define MM (BB * SS)      // 4096 rows
#define NQKV (3 * EE)     // 3072

// ---------------- scratch (static device globals; no allocation) ----------------
__device__ float g_q[BB * HH * SS * DD];   // [B,H,S,D]
__device__ float g_k[BB * HH * SS * DD];
__device__ float g_v[BB * HH * SS * DD];
__device__ float g_ctx[MM * EE];           // [B,S,E] attention context pre-proj

// ---------------- tf32 helpers ----------------
__device__ __forceinline__ uint32_t f2tf32(float x) {
    uint32_t r;
    asm("cvt.rna.tf32.f32 %0, %1;" : "=r"(r) : "f"(x));
    return r;
}

__device__ __forceinline__ void mma_tf32(float* c, const uint32_t* a, const uint32_t* b) {
    asm volatile(
        "mma.sync.aligned.m16n8k8.row.col.f32.tf32.tf32.f32 "
        "{%0,%1,%2,%3}, {%4,%5,%6,%7}, {%8,%9}, {%0,%1,%2,%3};"
        : "+f"(c[0]), "+f"(c[1]), "+f"(c[2]), "+f"(c[3])
        : "r"(a[0]), "r"(a[1]), "r"(a[2]), "r"(a[3]),
          "r"(b[0]), "r"(b[1]));
}

#define PITCH 136   // 136 % 32 == 8 -> conflict-free fragment LDS across thread-groups

// =================================================================================
// Kernel 1: QKV = X @ W + b via tf32 mma with 3-term error-compensated split,
// scattered into g_q/g_k/g_v as [B,H,S,D].
// Block 128x128, BK=16, 8 warps, warp tile 64x32 (4 m-tiles x 4 n-tiles of 16x8).
// =================================================================================
__global__ __launch_bounds__(256, 2) void qkv_gemm_tf32(
    const float* __restrict__ X, const float* __restrict__ W,
    const float* __restrict__ bias)
{
    __shared__ float Ah[16][PITCH], Al[16][PITCH];
    __shared__ float Bh[16][PITCH], Bl[16][PITCH];

    const int bn = blockIdx.x, bm = blockIdx.y;
    const int tid = threadIdx.x;
    const int warp = tid >> 5, lane = tid & 31;
    const int g = lane >> 2, tg = lane & 3;
    const int wm = (warp >> 2) * 64;     // 0 or 64
    const int wn = (warp & 3) * 32;      // 0,32,64,96
    const int row0 = bm * 128, col0 = bn * 128;

    float C[4][4][4];
#pragma unroll
    for (int mi = 0; mi < 4; mi++)
#pragma unroll
        for (int ni = 0; ni < 4; ni++)
#pragma unroll
            for (int t = 0; t < 4; t++) C[mi][ni][t] = 0.f;

    for (int k0 = 0; k0 < EE; k0 += 16) {
        // A tile 128x16 -> split + transpose into Ah/Al[k][m]
#pragma unroll
        for (int it = 0; it < 2; it++) {
            int f4 = tid + it * 256;            // 0..511
            int r = f4 >> 2;
            int c = (f4 & 3) << 2;
            float4 v = *(const float4*)(X + (size_t)(row0 + r) * EE + k0 + c);
            float xs[4] = {v.x, v.y, v.z, v.w};
#pragma unroll
            for (int j = 0; j < 4; j++) {
                float hf = __uint_as_float(f2tf32(xs[j]));
                Ah[c + j][r] = hf;
                Al[c + j][r] = xs[j] - hf;
            }
        }
        // B tile 16x128 -> split into Bh/Bl[k][n]
#pragma unroll
        for (int it = 0; it < 2; it++) {
            int f4 = tid + it * 256;
            int kk = f4 >> 5;
            int c = (f4 & 31) << 2;
            float4 v = *(const float4*)(W + (size_t)(k0 + kk) * NQKV + col0 + c);
            float xs[4] = {v.x, v.y, v.z, v.w};
            float hf[4], lf[4];
#pragma unroll
            for (int j = 0; j < 4; j++) {
                hf[j] = __uint_as_float(f2tf32(xs[j]));
                lf[j] = xs[j] - hf[j];
            }
            *(float4*)&Bh[kk][c] = make_float4(hf[0], hf[1], hf[2], hf[3]);
            *(float4*)&Bl[kk][c] = make_float4(lf[0], lf[1], lf[2], lf[3]);
        }
        __syncthreads();

#pragma unroll
        for (int ks = 0; ks < 2; ks++) {
            const int kb = ks * 8;
            uint32_t ah[4][4], al[4][4], bh[4][2], bl[4][2];
#pragma unroll
            for (int mi = 0; mi < 4; mi++) {
                int m = wm + mi * 16 + g;
                ah[mi][0] = __float_as_uint(Ah[kb + tg][m]);
                ah[mi][1] = __float_as_uint(Ah[kb + tg][m + 8]);
                ah[mi][2] = __float_as_uint(Ah[kb + tg + 4][m]);
                ah[mi][3] = __float_as_uint(Ah[kb + tg + 4][m + 8]);
                al[mi][0] = __float_as_uint(Al[kb + tg][m]);
                al[mi][1] = __float_as_uint(Al[kb + tg][m + 8]);
                al[mi][2] = __float_as_uint(Al[kb + tg + 4][m]);
                al[mi][3] = __float_as_uint(Al[kb + tg + 4][m + 8]);
            }
#pragma unroll
            for (int ni = 0; ni < 4; ni++) {
                int n = wn + ni * 8 + g;
                bh[ni][0] = __float_as_uint(Bh[kb + tg][n]);
                bh[ni][1] = __float_as_uint(Bh[kb + tg + 4][n]);
                bl[ni][0] = __float_as_uint(Bl[kb + tg][n]);
                bl[ni][1] = __float_as_uint(Bl[kb + tg + 4][n]);
            }
#pragma unroll
            for (int mi = 0; mi < 4; mi++)
#pragma unroll
                for (int ni = 0; ni < 4; ni++) {
                    mma_tf32(C[mi][ni], ah[mi], bh[ni]);
                    mma_tf32(C[mi][ni], ah[mi], bl[ni]);
                    mma_tf32(C[mi][ni], al[mi], bh[ni]);
                }
        }
        __syncthreads();
    }

    // epilogue: add bias, scatter to [B,H,S,D]
#pragma unroll
    for (int mi = 0; mi < 4; mi++) {
#pragma unroll
        for (int half = 0; half < 2; half++) {
            int r = row0 + wm + mi * 16 + g + half * 8;
            int b_ = r >> 11;
            int s  = r & 2047;
#pragma unroll
            for (int ni = 0; ni < 4; ni++) {
#pragma unroll
                for (int c01 = 0; c01 < 2; c01++) {
                    int n = col0 + wn + ni * 8 + 2 * tg + c01;
                    float v = C[mi][ni][half * 2 + c01] + bias[n];
                    int which = n >> 10;
                    int e = n & 1023;
                    int h = e >> 6, d = e & 63;
                    float* dst = (which == 0) ? g_q : (which == 1) ? g_k : g_v;
                    dst[(size_t)(((b_ * HH) + h) * SS + s) * DD + d] = v;
                }
            }
        }
    }
}

// =================================================================================
// Kernel 3: out = ctx @ Wp + bp via tf32 mma (3-term split). 4096x1024x1024.
// =================================================================================
__global__ __launch_bounds__(256, 2) void proj_gemm_tf32(
    const float* __restrict__ W, const float* __restrict__ bias,
    float* __restrict__ out)
{
    __shared__ float Ah[16][PITCH], Al[16][PITCH];
    __shared__ float Bh[16][PITCH], Bl[16][PITCH];

    const int bn = blockIdx.x, bm = blockIdx.y;
    const int tid = threadIdx.x;
    const int warp = tid >> 5, lane = tid & 31;
    const int g = lane >> 2, tg = lane & 3;
    const int wm = (warp >> 2) * 64;
    const int wn = (warp & 3) * 32;
    const int row0 = bm * 128, col0 = bn * 128;

    float C[4][4][4];
#pragma unroll
    for (int mi = 0; mi < 4; mi++)
#pragma unroll
        for (int ni = 0; ni < 4; ni++)
#pragma unroll
            for (int t = 0; t < 4; t++) C[mi][ni][t] = 0.f;

    for (int k0 = 0; k0 < EE; k0 += 16) {
#pragma unroll
        for (int it = 0; it < 2; it++) {
            int f4 = tid + it * 256;
            int r = f4 >> 2;
            int c = (f4 & 3) << 2;
            float4 v = *(const float4*)(g_ctx + (size_t)(row0 + r) * EE + k0 + c);
            float xs[4] = {v.x, v.y, v.z, v.w};
#pragma unroll
            for (int j = 0; j < 4; j++) {
                float hf = __uint_as_float(f2tf32(xs[j]));
                Ah[c + j][r] = hf;
                Al[c + j][r] = xs[j] - hf;
            }
        }
#pragma unroll
        for (int it = 0; it < 2; it++) {
            int f4 = tid + it * 256;
            int kk = f4 >> 5;
            int c = (f4 & 31) << 2;
            float4 v = *(const float4*)(W + (size_t)(k0 + kk) * EE + col0 + c);
            float xs[4] = {v.x, v.y, v.z, v.w};
            float hf[4], lf[4];
#pragma unroll
            for (int j = 0; j < 4; j++) {
                hf[j] = __uint_as_float(f2tf32(xs[j]));
                lf[j] = xs[j] - hf[j];
            }
            *(float4*)&Bh[kk][c] = make_float4(hf[0], hf[1], hf[2], hf[3]);
            *(float4*)&Bl[kk][c] = make_float4(lf[0], lf[1], lf[2], lf[3]);
        }
        __syncthreads();

#pragma unroll
        for (int ks = 0; ks < 2; ks++) {
            const int kb = ks * 8;
            uint32_t ah[4][4], al[4][4], bh[4][2], bl[4][2];
#pragma unroll
            for (int mi = 0; mi < 4; mi++) {
                int m = wm + mi * 16 + g;
                ah[mi][0] = __float_as_uint(Ah[kb + tg][m]);
                ah[mi][1] = __float_as_uint(Ah[kb + tg][m + 8]);
                ah[mi][2] = __float_as_uint(Ah[kb + tg + 4][m]);
                ah[mi][3] = __float_as_uint(Ah[kb + tg + 4][m + 8]);
                al[mi][0] = __float_as_uint(Al[kb + tg][m]);
                al[mi][1] = __float_as_uint(Al[kb + tg][m + 8]);
                al[mi][2] = __float_as_uint(Al[kb + tg + 4][m]);
                al[mi][3] = __float_as_uint(Al[kb + tg + 4][m + 8]);
            }
#pragma unroll
            for (int ni = 0; ni < 4; ni++) {
                int n = wn + ni * 8 + g;
                bh[ni][0] = __float_as_uint(Bh[kb + tg][n]);
                bh[ni][1] = __float_as_uint(Bh[kb + tg + 4][n]);
                bl[ni][0] = __float_as_uint(Bl[kb + tg][n]);
                bl[ni][1] = __float_as_uint(Bl[kb + tg + 4][n]);
            }
#pragma unroll
            for (int mi = 0; mi < 4; mi++)
#pragma unroll
                for (int ni = 0; ni < 4; ni++) {
                    mma_tf32(C[mi][ni], ah[mi], bh[ni]);
                    mma_tf32(C[mi][ni], ah[mi], bl[ni]);
                    mma_tf32(C[mi][ni], al[mi], bh[ni]);
                }
        }
        __syncthreads();
    }

#pragma unroll
    for (int mi = 0; mi < 4; mi++) {
#pragma unroll
        for (int half = 0; half < 2; half++) {
            int r = row0 + wm + mi * 16 + g + half * 8;
#pragma unroll
            for (int ni = 0; ni < 4; ni++) {
#pragma unroll
                for (int c01 = 0; c01 < 2; c01++) {
                    int n = col0 + wn + ni * 8 + 2 * tg + c01;
                    out[(size_t)r * EE + n] = C[mi][ni][half * 2 + c01] + bias[n];
                }
            }
        }
    }
}

// =================================================================================
// Kernel 2: fused causal attention (unchanged fp32 from R1 — R3 target).
// =================================================================================
#define QS_OFF 0
#define KS_OFF (64 * 132)
#define VS_OFF (KS_OFF + 64 * 132)
#define PS_OFF (VS_OFF + 128 * 68)
#define SMEM_FLOATS (PS_OFF + 128 * 132)
#define SMEM_BYTES (SMEM_FLOATS * 4)

extern __shared__ float smbuf[];

__global__ __launch_bounds__(256) void attn_kernel(float* __restrict__ attn_w)
{
    float* Qs = smbuf + QS_OFF;
    float* Ks = smbuf + KS_OFF;
    float* Vs = smbuf + VS_OFF;
    float* Ps = smbuf + PS_OFF;

    const int qb = blockIdx.x, h = blockIdx.y, b = blockIdx.z;
    const int tid = threadIdx.x;
    const int tx = tid & 15, ty = tid >> 4;
    const float scale = 0.125f;

    const float* Qg = g_q + (size_t)((b * HH + h) * SS) * DD;
    const float* Kg = g_k + (size_t)((b * HH + h) * SS) * DD;
    const float* Vg = g_v + (size_t)((b * HH + h) * SS) * DD;

#pragma unroll
    for (int it = 0; it < 8; it++) {
        int f4 = tid + it * 256;
        int r = f4 >> 4;
        int c = (f4 & 15) << 2;
        float4 v = *(const float4*)(Qg + (size_t)(qb * 128 + r) * DD + c);
        Qs[(c + 0) * 132 + r] = v.x; Qs[(c + 1) * 132 + r] = v.y;
        Qs[(c + 2) * 132 + r] = v.z; Qs[(c + 3) * 132 + r] = v.w;
    }
    __syncthreads();

    float m_run[8], l_run[8];
#pragma unroll
    for (int i = 0; i < 8; i++) { m_run[i] = -INFINITY; l_run[i] = 0.f; }

    // pass 1: row stats
    for (int kb = 0; kb <= qb; kb++) {
#pragma unroll
        for (int it = 0; it < 8; it++) {
            int f4 = tid + it * 256;
            int r = f4 >> 4;
            int c = (f4 & 15) << 2;
            float4 v = *(const float4*)(Kg + (size_t)(kb * 128 + r) * DD + c);
            Ks[(c + 0) * 132 + r] = v.x; Ks[(c + 1) * 132 + r] = v.y;
            Ks[(c + 2) * 132 + r] = v.z; Ks[(c + 3) * 132 + r] = v.w;
        }
        __syncthreads();

        float acc[8][8];
#pragma unroll
        for (int i = 0; i < 8; i++)
#pragma unroll
            for (int j = 0; j < 8; j++) acc[i][j] = 0.f;

#pragma unroll 8
        for (int d = 0; d < 64; d++) {
            float a[8], bb[8];
            *(float4*)(a)      = *(float4*)&Qs[d * 132 + ty * 4];
            *(float4*)(a + 4)  = *(float4*)&Qs[d * 132 + 64 + ty * 4];
            *(float4*)(bb)     = *(float4*)&Ks[d * 132 + tx * 4];
            *(float4*)(bb + 4) = *(float4*)&Ks[d * 132 + 64 + tx * 4];
#pragma unroll
            for (int i = 0; i < 8; i++)
#pragma unroll
                for (int j = 0; j < 8; j++) acc[i][j] += a[i] * bb[j];
        }

        const bool diag = (kb == qb);
#pragma unroll
        for (int i = 0; i < 8; i++) {
            int r = ((i & 4) ? 64 : 0) + (ty << 2) + (i & 3);
            float s8[8];
            float mloc = -INFINITY;
#pragma unroll
            for (int j = 0; j < 8; j++) {
                int c = ((j & 4) ? 64 : 0) + (tx << 2) + (j & 3);
                float sv = acc[i][j] * scale;
                if (diag && c > r) sv = -INFINITY;
                s8[j] = sv;
                mloc = fmaxf(mloc, sv);
            }
#pragma unroll
            for (int o = 1; o < 16; o <<= 1)
                mloc = fmaxf(mloc, __shfl_xor_sync(0xffffffffu, mloc, o));
            float m_new = fmaxf(m_run[i], mloc);
            float lsum = 0.f;
#pragma unroll
            for (int j = 0; j < 8; j++) lsum += __expf(s8[j] - m_new);
#pragma unroll
            for (int o = 1; o < 16; o <<= 1)
                lsum += __shfl_xor_sync(0xffffffffu, lsum, o);
            l_run[i] = l_run[i] * __expf(m_run[i] - m_new) + lsum;
            m_run[i] = m_new;
        }
        __syncthreads();
    }

    float inv_l[8];
#pragma unroll
    for (int i = 0; i < 8; i++) inv_l[i] = 1.f / l_run[i];

    float accO[8][4];
#pragma unroll
    for (int i = 0; i < 8; i++)
#pragma unroll
        for (int j = 0; j < 4; j++) accO[i][j] = 0.f;

    const size_t wbase_bh = (size_t)(b * HH + h) * SS * SS;

    // pass 2: exact probs + O
    for (int kb = 0; kb <= qb; kb++) {
#pragma unroll
        for (int it = 0; it < 8; it++) {
            int f4 = tid + it * 256;
            int r = f4 >> 4;
            int c = (f4 & 15) << 2;
            float4 v = *(const float4*)(Kg + (size_t)(kb * 128 + r) * DD + c);
            Ks[(c + 0) * 132 + r] = v.x; Ks[(c + 1) * 132 + r] = v.y;
            Ks[(c + 2) * 132 + r] = v.z; Ks[(c + 3) * 132 + r] = v.w;
            *(float4*)&Vs[r * 68 + c] = *(const float4*)(Vg + (size_t)(kb * 128 + r) * DD + c);
        }
        __syncthreads();

        float acc[8][8];
#pragma unroll
        for (int i = 0; i < 8; i++)
#pragma unroll
            for (int j = 0; j < 8; j++) acc[i][j] = 0.f;

#pragma unroll 8
        for (int d = 0; d < 64; d++) {
            float a[8], bb[8];
            *(float4*)(a)      = *(float4*)&Qs[d * 132 + ty * 4];
            *(float4*)(a + 4)  = *(float4*)&Qs[d * 132 + 64 + ty * 4];
            *(float4*)(bb)     = *(float4*)&Ks[d * 132 + tx * 4];
            *(float4*)(bb + 4) = *(float4*)&Ks[d * 132 + 64 + tx * 4];
#pragma unroll
            for (int i = 0; i < 8; i++)
#pragma unroll
                for (int j = 0; j < 8; j++) acc[i][j] += a[i] * bb[j];
        }

        const bool diag = (kb == qb);
#pragma unroll
        for (int i = 0; i < 8; i++) {
            int r = ((i & 4) ? 64 : 0) + (ty << 2) + (i & 3);
            float p[8];
#pragma unroll
            for (int j = 0; j < 8; j++) {
                int c = ((j & 4) ? 64 : 0) + (tx << 2) + (j & 3);
                float sv = acc[i][j] * scale;
                float pv = (diag && c > r) ? 0.f : __expf(sv - m_run[i]) * inv_l[i];
                p[j] = pv;
                Ps[r * 132 + c] = pv;
            }
            size_t gb = wbase_bh + (size_t)(qb * 128 + r) * SS + kb * 128;
            *(float4*)(attn_w + gb + tx * 4)      = make_float4(p[0], p[1], p[2], p[3]);
            *(float4*)(attn_w + gb + 64 + tx * 4) = make_float4(p[4], p[5], p[6], p[7]);
        }
        __syncthreads();

#pragma unroll 8
        for (int k = 0; k < 128; k++) {
            float bv[4];
            *(float4*)bv = *(float4*)&Vs[k * 68 + tx * 4];
#pragma unroll
            for (int i = 0; i < 8; i++) {
                int r = ((i & 4) ? 64 : 0) + (ty << 2) + (i & 3);
                float pv = Ps[r * 132 + k];
#pragma unroll
                for (int j = 0; j < 4; j++) accO[i][j] += pv * bv[j];
            }
        }
        __syncthreads();
    }

    const float4 z4 = make_float4(0.f, 0.f, 0.f, 0.f);
    for (int kb = qb + 1; kb < SS / 128; kb++) {
#pragma unroll
        for (int i = 0; i < 8; i++) {
            int r = ((i & 4) ? 64 : 0) + (ty << 2) + (i & 3);
            size_t gb = wbase_bh + (size_t)(qb * 128 + r) * SS + kb * 128;
            *(float4*)(attn_w + gb + tx * 4)      = z4;
            *(float4*)(attn_w + gb + 64 + tx * 4) = z4;
        }
    }

#pragma unroll
    for (int i = 0; i < 8; i++) {
        int r = ((i & 4) ? 64 : 0) + (ty << 2) + (i & 3);
        int q = qb * 128 + r;
        size_t base = (size_t)(b * SS + q) * EE + h * 64 + tx * 4;
        *(float4*)&g_ctx[base] = make_float4(accO[i][0], accO[i][1], accO[i][2], accO[i][3]);
    }
}

// =================================================================================
// launch
// =================================================================================
extern "C" void kernel_launch(void* const* d_in, const int* in_sizes, int n_in,
                              void* d_out, int out_size)
{
    const float* hs = (const float*)d_in[0];
    const float* aw = (const float*)d_in[1];
    const float* ab = (const float*)d_in[2];
    const float* pw = (const float*)d_in[3];
    const float* pb = (const float*)d_in[4];

    float* out      = (float*)d_out;
    float* attn_out = out;                         // [2,2048,1024]
    float* attn_w   = out + (size_t)MM * EE;       // [2,16,2048,2048]

    cudaFuncSetAttribute(attn_kernel, cudaFuncAttributeMaxDynamicSharedMemorySize,
                         SMEM_BYTES);

    qkv_gemm_tf32<<<dim3(NQKV / 128, MM / 128), 256>>>(hs, aw, ab);
    attn_kernel<<<dim3(SS / 128, HH, BB), 256, SMEM_BYTES>>>(attn_w);
    proj_gemm_tf32<<<dim3(EE / 128, MM / 128), 256>>>(pw, pb, attn_out);
}